// round 13
// baseline (speedup 1.0000x reference)
#include <cuda_runtime.h>
#include <cuda_fp16.h>
#include <cstdint>
#include <cmath>

// Problem constants
#define BATCH 8
#define CHN 3
#define IMG 224
#define HP 112      // Hp = Wp = 112
#define FIN 12      // patch features
#define D 128       // hidden per direction
#define L 112       // scan length (both stages)
#define NSEQ 896    // Hp*B = Wp*B
#define M_TOT (L * NSEQ)   // 100352

// Scratch (device globals — no dynamic allocation allowed)
__device__ __half g_a2h[(size_t)M_TOT * 256];   // stage-1 out (half): GEMM A + k3 xprime
__device__ __half g_w2t[(size_t)768 * 256];     // W2 transposed+permuted [j*256+ch][k], half
__device__ __half g_u2h[(size_t)M_TOT * 768];   // GEMM out, cols j*256+ch (j-major)

__device__ __forceinline__ float sigmoidf_(float v) {
    float t;
    asm("tanh.approx.f32 %0, %1;" : "=f"(t) : "f"(v * 0.5f));
    return fmaf(t, 0.5f, 0.5f);
}

typedef unsigned long long u64t;
__device__ __forceinline__ u64t pack2(float a, float b) {
    u64t r; asm("mov.b64 %0,{%1,%2};" : "=l"(r) : "f"(a), "f"(b)); return r;
}
__device__ __forceinline__ u64t fma2(u64t a, u64t b, u64t c) {
    u64t d; asm("fma.rn.f32x2 %0,%1,%2,%3;" : "=l"(d) : "l"(a), "l"(b), "l"(c)); return d;
}
__device__ __forceinline__ void unpack2(u64t v, float& a, float& b) {
    asm("mov.b64 {%0,%1},%2;" : "=f"(a), "=f"(b) : "l"(v));
}

#define LDSM4(r0, r1, r2, r3, addr) \
    asm volatile("ldmatrix.sync.aligned.m8n8.x4.shared.b16 {%0,%1,%2,%3},[%4];" \
                 : "=r"(r0), "=r"(r1), "=r"(r2), "=r"(r3) : "r"(addr))
#define CP16(sm, gp) \
    asm volatile("cp.async.cg.shared.global [%0], [%1], 16;" :: "r"(sm), "l"(gp))
#define CP_COMMIT() asm volatile("cp.async.commit_group;")
#define CP_WAIT1()  asm volatile("cp.async.wait_group 1;")
#define CP_WAIT0()  asm volatile("cp.async.wait_group 0;")

// ---------------------------------------------------------------------------
// Kernel 1: fused W2->half transpose (dir0 blocks) + patch-extract + (x @ W1)
// + bidirectional SRU scan (k=4). f-paired fma2; float2 patch loads; shfl64
// broadcast; 8 CTAs/SM target.
// ---------------------------------------------------------------------------
__global__ void __launch_bounds__(128, 8) k1_scan1(
    const float* __restrict__ x, const float* __restrict__ W1,
    const float* __restrict__ wc1, const float* __restrict__ b1,
    const float* __restrict__ W2)
{
    const int n1  = blockIdx.x;        // hp*8 + b
    const int dir = blockIdx.y;
    const int d   = threadIdx.x;       // 0..127 (output channel)
    const int lid = d & 31;
    const int hp  = n1 >> 3;
    const int b   = n1 & 7;

    // --- merged k0: W2[k][n] f32 -> g_w2t[(n%3)*256+n/3][k] half ---
    if (dir == 0 && n1 < 768) {
#pragma unroll
        for (int q = 0; q < 2; q++) {
            const int idx = n1 * 256 + q * 128 + d;    // k*768 + n
            const int k = idx / 768;
            const int n = idx % 768;
            const int np = (n % 3) * 256 + n / 3;
            g_w2t[(size_t)np * 256 + k] = __float2half(W2[idx]);
        }
    }

    // weights: f-paired, per output j: wp2[j][fp] = (w[2fp][j], w[2fp+1][j])
    u64t wp2[4][FIN / 2];
    const int col0 = (dir * D + d) * 4;
#pragma unroll
    for (int fp = 0; fp < FIN / 2; fp++) {
#pragma unroll
        for (int j = 0; j < 4; j++) {
            wp2[j][fp] = pack2(W1[(2 * fp) * 1024 + col0 + j],
                               W1[(2 * fp + 1) * 1024 + col0 + j]);
        }
    }
    const int chg = dir * D + d;
    const float vf = wc1[chg];
    const float vr = wc1[256 + chg];
    const float bf = b1[chg];
    const float br = b1[256 + chg];

    const int l0 = dir ? (L - 1) : 0;
    const int dl = dir ? -1 : 1;

    // lanes 0..5 each own a feature PAIR fp: f=2fp (ww=0) and f=2fp+1 (ww=1),
    // which are adjacent in x -> single float2 load, pre-packed once.
    int xrowbase = 0;
    u64t nv = 0ull;
    if (lid < FIN / 2) {
        const int c  = lid >> 1;          // fp = c*2 + wh
        const int wh = lid & 1;
        xrowbase = ((b * 3 + c) * IMG + 2 * hp + wh) * IMG;
        const float2 v = *(const float2*)(x + xrowbase + 2 * l0);
        nv = pack2(v.x, v.y);
    }

    size_t oidx = ((size_t)hp * NSEQ + l0 * 8 + b) * 256 + chg;
    const ptrdiff_t ostep = (ptrdiff_t)dl * 8 * 256;

    float cst = 0.0f;
    for (int s = 0; s < L; s++) {
        const u64t cv = nv;
        if (lid < FIN / 2 && (s + 1) < L) {
            const float2 v = *(const float2*)(x + xrowbase + 2 * (l0 + dl * (s + 1)));
            nv = pack2(v.x, v.y);
        }
        u64t a0 = 0ull, a1 = 0ull, a2 = 0ull, a3 = 0ull;
#pragma unroll
        for (int fp = 0; fp < FIN / 2; fp++) {
            const u64t pp = __shfl_sync(0xffffffffu, cv, fp);
            a0 = fma2(pp, wp2[0][fp], a0);
            a1 = fma2(pp, wp2[1][fp], a1);
            a2 = fma2(pp, wp2[2][fp], a2);
            a3 = fma2(pp, wp2[3][fp], a3);
        }
        float x0, y0, x1, y1, x2, y2, x3, y3;
        unpack2(a0, x0, y0);
        unpack2(a1, x1, y1);
        unpack2(a2, x2, y2);
        unpack2(a3, x3, y3);
        const float u0 = x0 + y0;
        const float u1 = x1 + y1;
        const float u2 = x2 + y2;
        const float u3 = x3 + y3;

        const float fg = sigmoidf_(u1 + vf * cst + bf);
        cst = fg * (cst - u0) + u0;
        const float rg = sigmoidf_(u2 + vr * cst + br);
        const float h  = rg * (cst - u3) + u3;
        g_a2h[oidx] = __float2half(h);
        oidx += ostep;
    }
}

// ---------------------------------------------------------------------------
// Kernel 2: fp16 GEMM  U2[100352,768] = a2h @ w2t^T
// BM=128, BN=128, BK=32; 256 threads; warp tile 32x64; ldmatrix + m16n8k16.
// cp.async 3-stage pipeline (dynamic smem, 60KB). [R8 config — HMMA wall]
// ---------------------------------------------------------------------------
#define SAH 40                      // halves per smem row (80B, LDSM conflict-free)
#define STGB (128 * SAH * 2)        // bytes per stage per matrix (10240)
__global__ void __launch_bounds__(256, 2) k2_gemm_f16()
{
    extern __shared__ char k2smem[];
    __half* As = (__half*)k2smem;                 // 3 stages
    __half* Bs = (__half*)(k2smem + 3 * STGB);    // 3 stages

    const int tid  = threadIdx.x;
    const int lane = tid & 31;
    const int gid  = lane >> 2;     // 0..7
    const int tig  = lane & 3;      // 0..3
    const int warp = tid >> 5;
    const int wm   = (warp & 3) * 32;   // warp m offset
    const int wn   = (warp >> 2) * 64;  // warp n offset
    const int n0   = blockIdx.x * 128;
    const int m0   = blockIdx.y * 128;

    const int row = tid >> 1;           // 0..127
    const int kc  = (tid & 1) * 16;     // half-offset within 32-wide ktile

    const __half* Ag = g_a2h + (size_t)(m0 + row) * 256 + kc;
    const __half* Bg = g_w2t + (size_t)(n0 + row) * 256 + kc;

    const unsigned sa = (unsigned)__cvta_generic_to_shared(As + row * SAH + kc);
    const unsigned sb = (unsigned)__cvta_generic_to_shared(Bs + row * SAH + kc);

    // ldmatrix base addresses (stage 0, kk = 0)
    const unsigned aAddr = (unsigned)__cvta_generic_to_shared(As)
        + (((wm + (lane & 7) + (lane & 8)) * SAH + ((lane & 16) ? 8 : 0)) * 2);
    const unsigned bAddr = (unsigned)__cvta_generic_to_shared(Bs)
        + (((wn + (lane & 7) + ((lane & 16) ? 8 : 0)) * SAH + ((lane & 8) ? 8 : 0)) * 2);

    // prologue: stages 0,1 (ktiles 0,1)
#pragma unroll
    for (int s = 0; s < 2; s++) {
        CP16(sa + s * STGB,      Ag + s * 32);
        CP16(sa + s * STGB + 16, Ag + s * 32 + 8);
        CP16(sb + s * STGB,      Bg + s * 32);
        CP16(sb + s * STGB + 16, Bg + s * 32 + 8);
        CP_COMMIT();
    }

    float c[2][8][4];
#pragma unroll
    for (int mi = 0; mi < 2; mi++)
#pragma unroll
        for (int ni = 0; ni < 8; ni++)
#pragma unroll
            for (int j = 0; j < 4; j++) c[mi][ni][j] = 0.f;

    for (int kt = 0; kt < 8; kt++) {
        if (kt == 7) { CP_WAIT0(); } else { CP_WAIT1(); }
        __syncthreads();

        if (kt < 6) {
            const int s  = (kt + 2) % 3;
            const int k0 = (kt + 2) * 32;
            CP16(sa + s * STGB,      Ag + k0);
            CP16(sa + s * STGB + 16, Ag + k0 + 8);
            CP16(sb + s * STGB,      Bg + k0);
            CP16(sb + s * STGB + 16, Bg + k0 + 8);
            CP_COMMIT();
        }

        const unsigned aB = aAddr + (kt % 3) * STGB;
        const unsigned bB = bAddr + (kt % 3) * STGB;
#pragma unroll
        for (int kk = 0; kk < 32; kk += 16) {
            unsigned a[2][4];
#pragma unroll
            for (int mi = 0; mi < 2; mi++)
                LDSM4(a[mi][0], a[mi][1], a[mi][2], a[mi][3],
                      aB + mi * (16 * SAH * 2) + kk * 2);
#pragma unroll
            for (int nt = 0; nt < 4; nt++) {
                unsigned b00, b01, b10, b11;
                LDSM4(b00, b01, b10, b11, bB + nt * (16 * SAH * 2) + kk * 2);
#pragma unroll
                for (int mi = 0; mi < 2; mi++) {
                    asm volatile(
                        "mma.sync.aligned.m16n8k16.row.col.f32.f16.f16.f32 "
                        "{%0,%1,%2,%3}, {%4,%5,%6,%7}, {%8,%9}, {%0,%1,%2,%3};"
                        : "+f"(c[mi][2 * nt][0]), "+f"(c[mi][2 * nt][1]),
                          "+f"(c[mi][2 * nt][2]), "+f"(c[mi][2 * nt][3])
                        : "r"(a[mi][0]), "r"(a[mi][1]), "r"(a[mi][2]), "r"(a[mi][3]),
                          "r"(b00), "r"(b01));
                    asm volatile(
                        "mma.sync.aligned.m16n8k16.row.col.f32.f16.f16.f32 "
                        "{%0,%1,%2,%3}, {%4,%5,%6,%7}, {%8,%9}, {%0,%1,%2,%3};"
                        : "+f"(c[mi][2 * nt + 1][0]), "+f"(c[mi][2 * nt + 1][1]),
                          "+f"(c[mi][2 * nt + 1][2]), "+f"(c[mi][2 * nt + 1][3])
                        : "r"(a[mi][0]), "r"(a[mi][1]), "r"(a[mi][2]), "r"(a[mi][3]),
                          "r"(b10), "r"(b11));
                }
            }
        }
    }

#pragma unroll
    for (int mi = 0; mi < 2; mi++) {
#pragma unroll
        for (int ni = 0; ni < 8; ni++) {
            const int r0  = m0 + wm + mi * 16 + gid;
            const int col = n0 + wn + ni * 8 + tig * 2;
            *(__half2*)(g_u2h + (size_t)r0 * 768 + col) =
                __floats2half2_rn(c[mi][ni][0], c[mi][ni][1]);
            *(__half2*)(g_u2h + (size_t)(r0 + 8) * 768 + col) =
                __floats2half2_rn(c[mi][ni][2], c[mi][ni][3]);
        }
    }
}

// ---------------------------------------------------------------------------
// Kernel 3: bidirectional SRU scan (k=3) + coalesced output, sw-pipelined,
// half2 channel-pairs, 4-step groups (reg-slim). Block 128 = 16 wp x 8 pairs.
// [R10 config]
// ---------------------------------------------------------------------------
__global__ void __launch_bounds__(128) k3_scan2(
    const float* __restrict__ wc2, const float* __restrict__ b2,
    float* __restrict__ out)
{
    const int tid = threadIdx.x;
    const int tcp = tid & 7;           // ch-pair within group
    const int tw  = tid >> 3;          // wp within group (0..15)
    const int bz  = blockIdx.z;
    const int b   = bz >> 1;
    const int dir = bz & 1;
    const int wp  = blockIdx.x * 16 + tw;
    const int cg  = blockIdx.y * 16 + tcp * 2;     // even channel index
    const int ch  = dir * D + cg;
    const int n2  = wp * 8 + b;

    const float2 vf = *(const float2*)(wc2 + ch);
    const float2 vr = *(const float2*)(wc2 + 256 + ch);
    const float2 bf = *(const float2*)(b2 + ch);
    const float2 br = *(const float2*)(b2 + 256 + ch);
    const float SC = 1.41421356237309515f;

    const int l0 = dir ? (L - 1) : 0;
    const int dl = dir ? -1 : 1;

    __shared__ float hs[4][16][17];

    const int ow = tid & 15;
    const int oc = tid >> 4;   // 0..7 (handles oc and oc+8)
    float* ob0 = out + ((size_t)(b * 256 + dir * D + blockIdx.y * 16 + oc) * HP) * HP
                     + blockIdx.x * 16 + ow;
    float* ob1 = out + ((size_t)(b * 256 + dir * D + blockIdx.y * 16 + oc + 8) * HP) * HP
                     + blockIdx.x * 16 + ow;

    const ptrdiff_t ustep = (ptrdiff_t)dl * (NSEQ * 768 / 2);   // half2 units
    const ptrdiff_t astep = (ptrdiff_t)dl * (NSEQ * 256 / 2);
    const __half2* ub = (const __half2*)(g_u2h + ((size_t)l0 * NSEQ + n2) * 768 + ch);
    const __half2* ab = (const __half2*)(g_a2h + ((size_t)l0 * NSEQ + n2) * 256 + ch);

    __half2 cu0[4], cu1[4], cu2[4], cxp[4];
    __half2 pu0[4], pu1[4], pu2[4], pxp[4];

#pragma unroll
    for (int j = 0; j < 4; j++) {
        const __half2* up = ub + (ptrdiff_t)j * ustep;
        cu0[j] = up[0];
        cu1[j] = up[128];
        cu2[j] = up[256];
        cxp[j] = ab[(ptrdiff_t)j * astep];
    }

    float2 cst = make_float2(0.f, 0.f);
#pragma unroll 2
    for (int g = 0; g < 28; g++) {
        if (g < 27) {
#pragma unroll
            for (int j = 0; j < 4; j++) {
                const int s = (g + 1) * 4 + j;
                const __half2* up = ub + (ptrdiff_t)s * ustep;
                pu0[j] = up[0];
                pu1[j] = up[128];
                pu2[j] = up[256];
                pxp[j] = ab[(ptrdiff_t)s * astep];
            }
        }
#pragma unroll
        for (int j = 0; j < 4; j++) {
            const float2 u0  = __half22float2(cu0[j]);
            const float2 u1  = __half22float2(cu1[j]);
            const float2 u2v = __half22float2(cu2[j]);
            const float2 xp  = __half22float2(cxp[j]);
            const float fg0 = sigmoidf_(u1.x + vf.x * cst.x + bf.x);
            const float fg1 = sigmoidf_(u1.y + vf.y * cst.y + bf.y);
            cst.x = fg0 * (cst.x - u0.x) + u0.x;
            cst.y = fg1 * (cst.y - u0.y) + u0.y;
            const float rg0 = sigmoidf_(u2v.x + vr.x * cst.x + br.x);
            const float rg1 = sigmoidf_(u2v.y + vr.y * cst.y + br.y);
            const float x0 = xp.x * SC, x1 = xp.y * SC;
            hs[j][tcp * 2][tw]     = rg0 * (cst.x - x0) + x0;
            hs[j][tcp * 2 + 1][tw] = rg1 * (cst.y - x1) + x1;
        }
        __syncthreads();
#pragma unroll
        for (int j = 0; j < 4; j++) {
            const int l = l0 + dl * (g * 4 + j);
            ob0[(size_t)l * HP] = hs[j][oc][ow];
            ob1[(size_t)l * HP] = hs[j][oc + 8][ow];
        }
        __syncthreads();
#pragma unroll
        for (int j = 0; j < 4; j++) {
            cu0[j] = pu0[j];
            cu1[j] = pu1[j];
            cu2[j] = pu2[j];
            cxp[j] = pxp[j];
        }
    }
}

// ---------------------------------------------------------------------------
extern "C" void kernel_launch(void* const* d_in, const int* in_sizes, int n_in,
                              void* d_out, int out_size)
{
    const float* x   = (const float*)d_in[0];
    const float* W1  = (const float*)d_in[1];
    const float* wc1 = (const float*)d_in[2];
    const float* b1  = (const float*)d_in[3];
    const float* W2  = (const float*)d_in[4];
    const float* wc2 = (const float*)d_in[5];
    const float* b2  = (const float*)d_in[6];
    float* out = (float*)d_out;

    cudaFuncSetAttribute(k2_gemm_f16, cudaFuncAttributeMaxDynamicSharedMemorySize,
                         6 * STGB);

    k1_scan1<<<dim3(NSEQ, 2), 128>>>(x, W1, wc1, b1, W2);
    k2_gemm_f16<<<dim3(768 / 128, M_TOT / 128), 256, 6 * STGB>>>();
    k3_scan2<<<dim3(HP / 16, 128 / 16, 16), 128>>>(wc2, b2, out);
}

// round 14
// speedup vs baseline: 1.0926x; 1.0926x over previous
#include <cuda_runtime.h>
#include <cuda_fp16.h>
#include <cstdint>
#include <cmath>

// Problem constants
#define BATCH 8
#define CHN 3
#define IMG 224
#define HP 112      // Hp = Wp = 112
#define FIN 12      // patch features
#define D 128       // hidden per direction
#define L 112       // scan length (both stages)
#define NSEQ 896    // Hp*B = Wp*B
#define M_TOT (L * NSEQ)   // 100352

// Scratch (device globals — no dynamic allocation allowed)
__device__ __half g_a2h[(size_t)M_TOT * 256];   // stage-1 out (half): GEMM A + k3 xprime
__device__ __half g_w2t[(size_t)768 * 256];     // W2 transposed+permuted [j*256+ch][k], half
__device__ __half g_u2h[(size_t)M_TOT * 768];   // GEMM out, cols j*256+ch (j-major)

__device__ __forceinline__ float sigmoidf_(float v) {
    float t;
    asm("tanh.approx.f32 %0, %1;" : "=f"(t) : "f"(v * 0.5f));
    return fmaf(t, 0.5f, 0.5f);
}

typedef unsigned long long u64t;
__device__ __forceinline__ u64t pack2(float a, float b) {
    u64t r; asm("mov.b64 %0,{%1,%2};" : "=l"(r) : "f"(a), "f"(b)); return r;
}
__device__ __forceinline__ u64t fma2(u64t a, u64t b, u64t c) {
    u64t d; asm("fma.rn.f32x2 %0,%1,%2,%3;" : "=l"(d) : "l"(a), "l"(b), "l"(c)); return d;
}
__device__ __forceinline__ void unpack2(u64t v, float& a, float& b) {
    asm("mov.b64 {%0,%1},%2;" : "=f"(a), "=f"(b) : "l"(v));
}

#define LDSM4(r0, r1, r2, r3, addr) \
    asm volatile("ldmatrix.sync.aligned.m8n8.x4.shared.b16 {%0,%1,%2,%3},[%4];" \
                 : "=r"(r0), "=r"(r1), "=r"(r2), "=r"(r3) : "r"(addr))
#define CP16(sm, gp) \
    asm volatile("cp.async.cg.shared.global [%0], [%1], 16;" :: "r"(sm), "l"(gp))
#define CP_COMMIT() asm volatile("cp.async.commit_group;")
#define CP_WAIT1()  asm volatile("cp.async.wait_group 1;")
#define CP_WAIT0()  asm volatile("cp.async.wait_group 0;")

// ---------------------------------------------------------------------------
// Kernel 1: fused W2->half transpose (dir0 blocks) + patch-extract + (x @ W1)
// + bidirectional SRU scan (k=4). f-paired fma2; float2 patch-pair loads;
// shfl64 broadcast. NO occupancy clamp (80 regs, no spills).
// ---------------------------------------------------------------------------
__global__ void __launch_bounds__(128) k1_scan1(
    const float* __restrict__ x, const float* __restrict__ W1,
    const float* __restrict__ wc1, const float* __restrict__ b1,
    const float* __restrict__ W2)
{
    const int n1  = blockIdx.x;        // hp*8 + b
    const int dir = blockIdx.y;
    const int d   = threadIdx.x;       // 0..127 (output channel)
    const int lid = d & 31;
    const int hp  = n1 >> 3;
    const int b   = n1 & 7;

    // --- merged k0: W2[k][n] f32 -> g_w2t[(n%3)*256+n/3][k] half ---
    if (dir == 0 && n1 < 768) {
#pragma unroll
        for (int q = 0; q < 2; q++) {
            const int idx = n1 * 256 + q * 128 + d;    // k*768 + n
            const int k = idx / 768;
            const int n = idx % 768;
            const int np = (n % 3) * 256 + n / 3;
            g_w2t[(size_t)np * 256 + k] = __float2half(W2[idx]);
        }
    }

    // weights: f-paired, per output j: wp2[j][fp] = (w[2fp][j], w[2fp+1][j])
    u64t wp2[4][FIN / 2];
    const int col0 = (dir * D + d) * 4;
#pragma unroll
    for (int fp = 0; fp < FIN / 2; fp++) {
#pragma unroll
        for (int j = 0; j < 4; j++) {
            wp2[j][fp] = pack2(W1[(2 * fp) * 1024 + col0 + j],
                               W1[(2 * fp + 1) * 1024 + col0 + j]);
        }
    }
    const int chg = dir * D + d;
    const float vf = wc1[chg];
    const float vr = wc1[256 + chg];
    const float bf = b1[chg];
    const float br = b1[256 + chg];

    const int l0 = dir ? (L - 1) : 0;
    const int dl = dir ? -1 : 1;

    // lanes 0..5 each own a feature PAIR fp = c*2 + wh: f=2fp (ww=0) and
    // f=2fp+1 (ww=1) are adjacent in x -> single float2 load, packed once.
    int xrowbase = 0;
    u64t nv = 0ull;
    if (lid < FIN / 2) {
        const int c  = lid >> 1;
        const int wh = lid & 1;
        xrowbase = ((b * 3 + c) * IMG + 2 * hp + wh) * IMG;
        const float2 v = *(const float2*)(x + xrowbase + 2 * l0);
        nv = pack2(v.x, v.y);
    }

    size_t oidx = ((size_t)hp * NSEQ + l0 * 8 + b) * 256 + chg;
    const ptrdiff_t ostep = (ptrdiff_t)dl * 8 * 256;

    float cst = 0.0f;
    for (int s = 0; s < L; s++) {
        const u64t cv = nv;
        if (lid < FIN / 2 && (s + 1) < L) {
            const float2 v = *(const float2*)(x + xrowbase + 2 * (l0 + dl * (s + 1)));
            nv = pack2(v.x, v.y);
        }
        u64t a0 = 0ull, a1 = 0ull, a2 = 0ull, a3 = 0ull;
#pragma unroll
        for (int fp = 0; fp < FIN / 2; fp++) {
            const u64t pp = __shfl_sync(0xffffffffu, cv, fp);
            a0 = fma2(pp, wp2[0][fp], a0);
            a1 = fma2(pp, wp2[1][fp], a1);
            a2 = fma2(pp, wp2[2][fp], a2);
            a3 = fma2(pp, wp2[3][fp], a3);
        }
        float x0, y0, x1, y1, x2, y2, x3, y3;
        unpack2(a0, x0, y0);
        unpack2(a1, x1, y1);
        unpack2(a2, x2, y2);
        unpack2(a3, x3, y3);
        const float u0 = x0 + y0;
        const float u1 = x1 + y1;
        const float u2 = x2 + y2;
        const float u3 = x3 + y3;

        const float fg = sigmoidf_(u1 + vf * cst + bf);
        cst = fg * (cst - u0) + u0;
        const float rg = sigmoidf_(u2 + vr * cst + br);
        const float h  = rg * (cst - u3) + u3;
        g_a2h[oidx] = __float2half(h);
        oidx += ostep;
    }
}

// ---------------------------------------------------------------------------
// Kernel 2: fp16 GEMM  U2[100352,768] = a2h @ w2t^T
// BM=128, BN=128, BK=32; 256 threads; warp tile 32x64; ldmatrix + m16n8k16.
// cp.async 3-stage pipeline (dynamic smem, 60KB). [R8 config — HMMA wall]
// ---------------------------------------------------------------------------
#define SAH 40                      // halves per smem row (80B, LDSM conflict-free)
#define STGB (128 * SAH * 2)        // bytes per stage per matrix (10240)
__global__ void __launch_bounds__(256, 2) k2_gemm_f16()
{
    extern __shared__ char k2smem[];
    __half* As = (__half*)k2smem;                 // 3 stages
    __half* Bs = (__half*)(k2smem + 3 * STGB);    // 3 stages

    const int tid  = threadIdx.x;
    const int lane = tid & 31;
    const int gid  = lane >> 2;     // 0..7
    const int tig  = lane & 3;      // 0..3
    const int warp = tid >> 5;
    const int wm   = (warp & 3) * 32;   // warp m offset
    const int wn   = (warp >> 2) * 64;  // warp n offset
    const int n0   = blockIdx.x * 128;
    const int m0   = blockIdx.y * 128;

    const int row = tid >> 1;           // 0..127
    const int kc  = (tid & 1) * 16;     // half-offset within 32-wide ktile

    const __half* Ag = g_a2h + (size_t)(m0 + row) * 256 + kc;
    const __half* Bg = g_w2t + (size_t)(n0 + row) * 256 + kc;

    const unsigned sa = (unsigned)__cvta_generic_to_shared(As + row * SAH + kc);
    const unsigned sb = (unsigned)__cvta_generic_to_shared(Bs + row * SAH + kc);

    // ldmatrix base addresses (stage 0, kk = 0)
    const unsigned aAddr = (unsigned)__cvta_generic_to_shared(As)
        + (((wm + (lane & 7) + (lane & 8)) * SAH + ((lane & 16) ? 8 : 0)) * 2);
    const unsigned bAddr = (unsigned)__cvta_generic_to_shared(Bs)
        + (((wn + (lane & 7) + ((lane & 16) ? 8 : 0)) * SAH + ((lane & 8) ? 8 : 0)) * 2);

    // prologue: stages 0,1 (ktiles 0,1)
#pragma unroll
    for (int s = 0; s < 2; s++) {
        CP16(sa + s * STGB,      Ag + s * 32);
        CP16(sa + s * STGB + 16, Ag + s * 32 + 8);
        CP16(sb + s * STGB,      Bg + s * 32);
        CP16(sb + s * STGB + 16, Bg + s * 32 + 8);
        CP_COMMIT();
    }

    float c[2][8][4];
#pragma unroll
    for (int mi = 0; mi < 2; mi++)
#pragma unroll
        for (int ni = 0; ni < 8; ni++)
#pragma unroll
            for (int j = 0; j < 4; j++) c[mi][ni][j] = 0.f;

    for (int kt = 0; kt < 8; kt++) {
        if (kt == 7) { CP_WAIT0(); } else { CP_WAIT1(); }
        __syncthreads();

        if (kt < 6) {
            const int s  = (kt + 2) % 3;
            const int k0 = (kt + 2) * 32;
            CP16(sa + s * STGB,      Ag + k0);
            CP16(sa + s * STGB + 16, Ag + k0 + 8);
            CP16(sb + s * STGB,      Bg + k0);
            CP16(sb + s * STGB + 16, Bg + k0 + 8);
            CP_COMMIT();
        }

        const unsigned aB = aAddr + (kt % 3) * STGB;
        const unsigned bB = bAddr + (kt % 3) * STGB;
#pragma unroll
        for (int kk = 0; kk < 32; kk += 16) {
            unsigned a[2][4];
#pragma unroll
            for (int mi = 0; mi < 2; mi++)
                LDSM4(a[mi][0], a[mi][1], a[mi][2], a[mi][3],
                      aB + mi * (16 * SAH * 2) + kk * 2);
#pragma unroll
            for (int nt = 0; nt < 4; nt++) {
                unsigned b00, b01, b10, b11;
                LDSM4(b00, b01, b10, b11, bB + nt * (16 * SAH * 2) + kk * 2);
#pragma unroll
                for (int mi = 0; mi < 2; mi++) {
                    asm volatile(
                        "mma.sync.aligned.m16n8k16.row.col.f32.f16.f16.f32 "
                        "{%0,%1,%2,%3}, {%4,%5,%6,%7}, {%8,%9}, {%0,%1,%2,%3};"
                        : "+f"(c[mi][2 * nt][0]), "+f"(c[mi][2 * nt][1]),
                          "+f"(c[mi][2 * nt][2]), "+f"(c[mi][2 * nt][3])
                        : "r"(a[mi][0]), "r"(a[mi][1]), "r"(a[mi][2]), "r"(a[mi][3]),
                          "r"(b00), "r"(b01));
                    asm volatile(
                        "mma.sync.aligned.m16n8k16.row.col.f32.f16.f16.f32 "
                        "{%0,%1,%2,%3}, {%4,%5,%6,%7}, {%8,%9}, {%0,%1,%2,%3};"
                        : "+f"(c[mi][2 * nt + 1][0]), "+f"(c[mi][2 * nt + 1][1]),
                          "+f"(c[mi][2 * nt + 1][2]), "+f"(c[mi][2 * nt + 1][3])
                        : "r"(a[mi][0]), "r"(a[mi][1]), "r"(a[mi][2]), "r"(a[mi][3]),
                          "r"(b10), "r"(b11));
                }
            }
        }
    }

#pragma unroll
    for (int mi = 0; mi < 2; mi++) {
#pragma unroll
        for (int ni = 0; ni < 8; ni++) {
            const int r0  = m0 + wm + mi * 16 + gid;
            const int col = n0 + wn + ni * 8 + tig * 2;
            *(__half2*)(g_u2h + (size_t)r0 * 768 + col) =
                __floats2half2_rn(c[mi][ni][0], c[mi][ni][1]);
            *(__half2*)(g_u2h + (size_t)(r0 + 8) * 768 + col) =
                __floats2half2_rn(c[mi][ni][2], c[mi][ni][3]);
        }
    }
}

// ---------------------------------------------------------------------------
// Kernel 3: bidirectional SRU scan (k=3) + coalesced output, sw-pipelined,
// half2 channel-pairs, 4-step groups (reg-slim). Block 128 = 16 wp x 8 pairs.
// [R10 config]
// ---------------------------------------------------------------------------
__global__ void __launch_bounds__(128) k3_scan2(
    const float* __restrict__ wc2, const float* __restrict__ b2,
    float* __restrict__ out)
{
    const int tid = threadIdx.x;
    const int tcp = tid & 7;           // ch-pair within group
    const int tw  = tid >> 3;          // wp within group (0..15)
    const int bz  = blockIdx.z;
    const int b   = bz >> 1;
    const int dir = bz & 1;
    const int wp  = blockIdx.x * 16 + tw;
    const int cg  = blockIdx.y * 16 + tcp * 2;     // even channel index
    const int ch  = dir * D + cg;
    const int n2  = wp * 8 + b;

    const float2 vf = *(const float2*)(wc2 + ch);
    const float2 vr = *(const float2*)(wc2 + 256 + ch);
    const float2 bf = *(const float2*)(b2 + ch);
    const float2 br = *(const float2*)(b2 + 256 + ch);
    const float SC = 1.41421356237309515f;

    const int l0 = dir ? (L - 1) : 0;
    const int dl = dir ? -1 : 1;

    __shared__ float hs[4][16][17];

    const int ow = tid & 15;
    const int oc = tid >> 4;   // 0..7 (handles oc and oc+8)
    float* ob0 = out + ((size_t)(b * 256 + dir * D + blockIdx.y * 16 + oc) * HP) * HP
                     + blockIdx.x * 16 + ow;
    float* ob1 = out + ((size_t)(b * 256 + dir * D + blockIdx.y * 16 + oc + 8) * HP) * HP
                     + blockIdx.x * 16 + ow;

    const ptrdiff_t ustep = (ptrdiff_t)dl * (NSEQ * 768 / 2);   // half2 units
    const ptrdiff_t astep = (ptrdiff_t)dl * (NSEQ * 256 / 2);
    const __half2* ub = (const __half2*)(g_u2h + ((size_t)l0 * NSEQ + n2) * 768 + ch);
    const __half2* ab = (const __half2*)(g_a2h + ((size_t)l0 * NSEQ + n2) * 256 + ch);

    __half2 cu0[4], cu1[4], cu2[4], cxp[4];
    __half2 pu0[4], pu1[4], pu2[4], pxp[4];

#pragma unroll
    for (int j = 0; j < 4; j++) {
        const __half2* up = ub + (ptrdiff_t)j * ustep;
        cu0[j] = up[0];
        cu1[j] = up[128];
        cu2[j] = up[256];
        cxp[j] = ab[(ptrdiff_t)j * astep];
    }

    float2 cst = make_float2(0.f, 0.f);
#pragma unroll 2
    for (int g = 0; g < 28; g++) {
        if (g < 27) {
#pragma unroll
            for (int j = 0; j < 4; j++) {
                const int s = (g + 1) * 4 + j;
                const __half2* up = ub + (ptrdiff_t)s * ustep;
                pu0[j] = up[0];
                pu1[j] = up[128];
                pu2[j] = up[256];
                pxp[j] = ab[(ptrdiff_t)s * astep];
            }
        }
#pragma unroll
        for (int j = 0; j < 4; j++) {
            const float2 u0  = __half22float2(cu0[j]);
            const float2 u1  = __half22float2(cu1[j]);
            const float2 u2v = __half22float2(cu2[j]);
            const float2 xp  = __half22float2(cxp[j]);
            const float fg0 = sigmoidf_(u1.x + vf.x * cst.x + bf.x);
            const float fg1 = sigmoidf_(u1.y + vf.y * cst.y + bf.y);
            cst.x = fg0 * (cst.x - u0.x) + u0.x;
            cst.y = fg1 * (cst.y - u0.y) + u0.y;
            const float rg0 = sigmoidf_(u2v.x + vr.x * cst.x + br.x);
            const float rg1 = sigmoidf_(u2v.y + vr.y * cst.y + br.y);
            const float x0 = xp.x * SC, x1 = xp.y * SC;
            hs[j][tcp * 2][tw]     = rg0 * (cst.x - x0) + x0;
            hs[j][tcp * 2 + 1][tw] = rg1 * (cst.y - x1) + x1;
        }
        __syncthreads();
#pragma unroll
        for (int j = 0; j < 4; j++) {
            const int l = l0 + dl * (g * 4 + j);
            ob0[(size_t)l * HP] = hs[j][oc][ow];
            ob1[(size_t)l * HP] = hs[j][oc + 8][ow];
        }
        __syncthreads();
#pragma unroll
        for (int j = 0; j < 4; j++) {
            cu0[j] = pu0[j];
            cu1[j] = pu1[j];
            cu2[j] = pu2[j];
            cxp[j] = pxp[j];
        }
    }
}

// ---------------------------------------------------------------------------
extern "C" void kernel_launch(void* const* d_in, const int* in_sizes, int n_in,
                              void* d_out, int out_size)
{
    const float* x   = (const float*)d_in[0];
    const float* W1  = (const float*)d_in[1];
    const float* wc1 = (const float*)d_in[2];
    const float* b1  = (const float*)d_in[3];
    const float* W2  = (const float*)d_in[4];
    const float* wc2 = (const float*)d_in[5];
    const float* b2  = (const float*)d_in[6];
    float* out = (float*)d_out;

    cudaFuncSetAttribute(k2_gemm_f16, cudaFuncAttributeMaxDynamicSharedMemorySize,
                         6 * STGB);

    k1_scan1<<<dim3(NSEQ, 2), 128>>>(x, W1, wc1, b1, W2);
    k2_gemm_f16<<<dim3(768 / 128, M_TOT / 128), 256, 6 * STGB>>>();
    k3_scan2<<<dim3(HP / 16, 128 / 16, 16), 128>>>(wc2, b2, out);
}